// round 6
// baseline (speedup 1.0000x reference)
#include <cuda_runtime.h>
#include <math.h>

#define En 2
#define NN 512
#define Bn 64
#define Tt 12
#define Kk 64
#define RN 8     // rows per block tile in main kernel
#define BG 4     // batches per block in main kernel
#define ESTR (Bn * NN * NN)   // e-stride in output

// Scratch (static device arrays: allocation-free)
__device__ __align__(16) float g_sup[En * NN * NN];      // relu(supports + adaptive)  (2 MB)
__device__ __align__(16) float g_nodesT[Bn * NN * Tt];   // normalized nodes, [b][n][t] (1.5 MB)
__device__ __align__(16) float g_nodesN[Bn * Tt * NN];   // normalized nodes, [b][t][n] (1.5 MB)

// ---------------- packed f32x2 + MUFU helpers ----------------
__device__ __forceinline__ unsigned long long pack2(float a, float b) {
    unsigned long long r;
    asm("mov.b64 %0, {%1, %2};" : "=l"(r) : "f"(a), "f"(b));
    return r;
}
__device__ __forceinline__ void unpack2(unsigned long long p, float& a, float& b) {
    asm("mov.b64 {%0, %1}, %2;" : "=f"(a), "=f"(b) : "l"(p));
}
__device__ __forceinline__ unsigned long long fma2_(unsigned long long a, unsigned long long b, unsigned long long c) {
    unsigned long long d;
    asm("fma.rn.f32x2 %0, %1, %2, %3;" : "=l"(d) : "l"(a), "l"(b), "l"(c));
    return d;
}
__device__ __forceinline__ unsigned long long mul2_(unsigned long long a, unsigned long long b) {
    unsigned long long d;
    asm("mul.rn.f32x2 %0, %1, %2;" : "=l"(d) : "l"(a), "l"(b));
    return d;
}
__device__ __forceinline__ unsigned long long add2_(unsigned long long a, unsigned long long b) {
    unsigned long long d;
    asm("add.rn.f32x2 %0, %1, %2;" : "=l"(d) : "l"(a), "l"(b));
    return d;
}
__device__ __forceinline__ float sqrt_ap(float x) { float r; asm("sqrt.approx.f32 %0, %1;" : "=f"(r) : "f"(x)); return r; }
__device__ __forceinline__ float ex2_neg(float x) { float r; asm("ex2.approx.f32 %0, %1;"  : "=f"(r) : "f"(-x)); return r; }
__device__ __forceinline__ float rcp_ap(float x)  { float r; asm("rcp.approx.f32 %0, %1;"  : "=f"(r) : "f"(x)); return r; }
__device__ __forceinline__ float hadd2(unsigned long long p) {
    float a, b; unpack2(p, a, b); return a + b;
}

// ---------------------------------------------------------------------------
// Kernel A (fused prep):
//   z = 0,1 : g_sup[e] = relu(supports + u * diag(s*softplus(bias)) * v^T)
//   z = 2   : L2-normalize node histories -> g_nodesT [b][n][t] + g_nodesN [b][t][n]
// ---------------------------------------------------------------------------
__global__ void __launch_bounds__(256) prep_kernel(const float* __restrict__ supports,
                                                   const float* __restrict__ u,
                                                   const float* __restrict__ s,
                                                   const float* __restrict__ v,
                                                   const float* __restrict__ bias,
                                                   const float* __restrict__ inputs) {
    const int tid = threadIdx.x;

    if (blockIdx.z == 2) {
        const int g = (blockIdx.y * 8 + blockIdx.x) * 256 + tid;
        #pragma unroll
        for (int it = 0; it < 2; it++) {
            const int i = g + it * 16384;      // b*512 + n
            const int b = i >> 9, n = i & (NN - 1);
            float x[Tt];
            float ss = 0.f;
            #pragma unroll
            for (int t = 0; t < Tt; t++) {
                x[t] = inputs[(((b * Tt + t) * NN) + n) * 2];
                ss = fmaf(x[t], x[t], ss);
            }
            float inv = 1.0f / fmaxf(sqrtf(ss), 1e-12f);
            #pragma unroll
            for (int t = 0; t < Tt; t++) x[t] *= inv;
            float* dst = g_nodesT + (b * NN + n) * Tt;
            *(float4*)(dst)     = make_float4(x[0], x[1], x[2],  x[3]);
            *(float4*)(dst + 4) = make_float4(x[4], x[5], x[6],  x[7]);
            *(float4*)(dst + 8) = make_float4(x[8], x[9], x[10], x[11]);
            #pragma unroll
            for (int t = 0; t < Tt; t++)
                g_nodesN[(b * Tt + t) * NN + n] = x[t];
        }
        return;
    }

    __shared__ float su_t[Kk][68];
    __shared__ float sv_t[Kk][68];
    __shared__ float ssc[Kk];

    const int e  = blockIdx.z;
    const int n0 = blockIdx.y * 64;
    const int m0 = blockIdx.x * 64;

    if (tid < 64) {
        float bx = bias[e * Kk + tid];
        float sp = (bx > 20.f) ? bx : log1pf(__expf(bx));   // softplus
        ssc[tid] = s[e * Kk + tid] * sp;
    }
    __syncthreads();

    #pragma unroll
    for (int j = 0; j < 4; j++) {
        int idx = tid + j * 256;
        int row = idx & 63;
        int kq  = idx >> 6;
        float4 uv = *(const float4*)(u + (e * NN + n0 + row) * Kk + kq * 4);
        float4 vv = *(const float4*)(v + (e * NN + m0 + row) * Kk + kq * 4);
        su_t[kq * 4 + 0][row] = uv.x * ssc[kq * 4 + 0];
        su_t[kq * 4 + 1][row] = uv.y * ssc[kq * 4 + 1];
        su_t[kq * 4 + 2][row] = uv.z * ssc[kq * 4 + 2];
        su_t[kq * 4 + 3][row] = uv.w * ssc[kq * 4 + 3];
        sv_t[kq * 4 + 0][row] = vv.x;
        sv_t[kq * 4 + 1][row] = vv.y;
        sv_t[kq * 4 + 2][row] = vv.z;
        sv_t[kq * 4 + 3][row] = vv.w;
    }
    __syncthreads();

    const int ry = (tid >> 4) << 2;
    const int rx = (tid & 15) << 2;
    float acc[4][4] = {};

    #pragma unroll
    for (int k = 0; k < 64; k++) {
        float4 a  = *(const float4*)&su_t[k][ry];
        float4 bq = *(const float4*)&sv_t[k][rx];
        acc[0][0] = fmaf(a.x, bq.x, acc[0][0]); acc[0][1] = fmaf(a.x, bq.y, acc[0][1]);
        acc[0][2] = fmaf(a.x, bq.z, acc[0][2]); acc[0][3] = fmaf(a.x, bq.w, acc[0][3]);
        acc[1][0] = fmaf(a.y, bq.x, acc[1][0]); acc[1][1] = fmaf(a.y, bq.y, acc[1][1]);
        acc[1][2] = fmaf(a.y, bq.z, acc[1][2]); acc[1][3] = fmaf(a.y, bq.w, acc[1][3]);
        acc[2][0] = fmaf(a.z, bq.x, acc[2][0]); acc[2][1] = fmaf(a.z, bq.y, acc[2][1]);
        acc[2][2] = fmaf(a.z, bq.z, acc[2][2]); acc[2][3] = fmaf(a.z, bq.w, acc[2][3]);
        acc[3][0] = fmaf(a.w, bq.x, acc[3][0]); acc[3][1] = fmaf(a.w, bq.y, acc[3][1]);
        acc[3][2] = fmaf(a.w, bq.z, acc[3][2]); acc[3][3] = fmaf(a.w, bq.w, acc[3][3]);
    }

    #pragma unroll
    for (int i = 0; i < 4; i++) {
        int base = (e * NN + n0 + ry + i) * NN + m0 + rx;
        float4 sp = *(const float4*)(supports + base);
        float4 o;
        o.x = fmaxf(sp.x + acc[i][0], 0.f);
        o.y = fmaxf(sp.y + acc[i][1], 0.f);
        o.z = fmaxf(sp.z + acc[i][2], 0.f);
        o.w = fmaxf(sp.w + acc[i][3], 0.f);
        *(float4*)(g_sup + base) = o;
    }
}

// ---------------------------------------------------------------------------
// Kernel C: fused main pass, e-split for occupancy.
// Block = (n-tile, batch-group, expert e). 256 threads, each owns an m-pair.
// sup & val register-resident; only xd + row-sum partials in smem.
// ---------------------------------------------------------------------------
__global__ void __launch_bounds__(256, 3)
main_kernel(float* __restrict__ out) {
    __shared__ float ps[RN][256];                     // row-sum partials, 8 KB
    __shared__ unsigned long long xd[RN * Tt];        // packed {xn,xn} per tile row
    __shared__ float invs[RN];

    const int tid  = threadIdx.x;
    const int lane = tid & 31;
    const int warp = tid >> 5;
    const int n0 = blockIdx.x * RN;
    const int b0 = blockIdx.y * BG;
    const int e  = blockIdx.z;
    const int m0 = tid * 2;

    // sup (relu'd) in registers: batch-invariant, this thread's m-pair, one e
    unsigned long long sup[RN];
    #pragma unroll
    for (int r = 0; r < RN; r++)
        sup[r] = *(const unsigned long long*)(g_sup + e * (NN * NN) + (n0 + r) * NN + m0);

    // 2 * (ln2^-1)^2
    const float C = 4.1627379620112154f;
    const unsigned long long CM = pack2(-C, -C);
    const unsigned long long CP = pack2( C,  C);

    for (int bi = 0; bi < BG; ++bi) {
        const int b = b0 + bi;

        // duplicated row-node table (96 values)
        if (tid < RN * Tt) {
            int r = tid / Tt, t = tid - r * Tt;
            float xv = g_nodesT[b * (NN * Tt) + (n0 + r) * Tt + t];
            xd[tid] = pack2(xv, xv);
        }

        // xm pair: 12 coalesced LDG.64, already packed {x[t][m0], x[t][m0+1]}
        unsigned long long xm2[Tt];
        {
            const unsigned long long* xb =
                (const unsigned long long*)(g_nodesN + b * (Tt * NN)) + tid;
            #pragma unroll
            for (int t = 0; t < Tt; t++)
                xm2[t] = xb[t * (NN / 2)];
        }
        __syncthreads();   // xd ready; also fences prev-batch writeout/reduce

        unsigned long long val[RN];
        #pragma unroll
        for (int r = 0; r < RN; r++) {
            const ulonglong2* xdp = (const ulonglong2*)&xd[r * Tt];
            ulonglong2 q0 = xdp[0], q1 = xdp[1], q2 = xdp[2];
            ulonglong2 q3 = xdp[3], q4 = xdp[4], q5 = xdp[5];
            unsigned long long pa = mul2_(xm2[0], q0.x);
            unsigned long long pb = mul2_(xm2[1], q0.y);
            pa = fma2_(xm2[2],  q1.x, pa);  pb = fma2_(xm2[3],  q1.y, pb);
            pa = fma2_(xm2[4],  q2.x, pa);  pb = fma2_(xm2[5],  q2.y, pb);
            pa = fma2_(xm2[6],  q3.x, pa);  pb = fma2_(xm2[7],  q3.y, pb);
            pa = fma2_(xm2[8],  q4.x, pa);  pb = fma2_(xm2[9],  q4.y, pb);
            pa = fma2_(xm2[10], q5.x, pa);  pb = fma2_(xm2[11], q5.y, pb);
            unsigned long long inner2 = add2_(pa, pb);
            unsigned long long d2p = fma2_(inner2, CM, CP);  // (1.4427*d)^2 packed
            float d20, d21;
            unpack2(d2p, d20, d21);
            d20 = fmaxf(d20, 0.f);
            d21 = fmaxf(d21, 0.f);
            float f0 = ex2_neg(sqrt_ap(d20)) + 1.0f;
            float f1 = ex2_neg(sqrt_ap(d21)) + 1.0f;

            val[r] = mul2_(pack2(f0, f1), sup[r]);
            ps[r][tid] = hadd2(val[r]);
        }
        __syncthreads();

        // One warp per row: 256 partials each (2 float4 per lane)
        {
            const float4* p0 = (const float4*)ps[warp];
            float4 v0 = p0[lane];
            float4 v1 = p0[lane + 32];
            float sum = (v0.x + v0.y) + (v0.z + v0.w)
                      + (v1.x + v1.y) + (v1.z + v1.w);
            #pragma unroll
            for (int o = 16; o > 0; o >>= 1)
                sum += __shfl_xor_sync(0xffffffffu, sum, o);
            if (lane == 0)
                invs[warp] = rcp_ap(fmaxf(sum, 1e-12f));
        }
        __syncthreads();

        // Direct register -> gmem writeout (STG.64, coalesced)
        float* ob = out + e * ESTR + (b * NN + n0) * NN + m0;
        #pragma unroll
        for (int r = 0; r < RN; r++) {
            float iv = invs[r];
            *(unsigned long long*)(ob + r * NN) = mul2_(val[r], pack2(iv, iv));
        }
    }
}

// ---------------------------------------------------------------------------
extern "C" void kernel_launch(void* const* d_in, const int* in_sizes, int n_in,
                              void* d_out, int out_size) {
    const float* supports = (const float*)d_in[0];  // [2,512,512]
    const float* u        = (const float*)d_in[1];  // [2,512,64]
    const float* s        = (const float*)d_in[2];  // [2,64]
    const float* v        = (const float*)d_in[3];  // [2,512,64]
    const float* bias     = (const float*)d_in[4];  // [2,64]
    const float* inputs   = (const float*)d_in[5];  // [64,12,512,2]
    float* out = (float*)d_out;                     // [2,64,512,512]

    prep_kernel<<<dim3(8, 8, 3), 256>>>(supports, u, s, v, bias, inputs);
    main_kernel<<<dim3(NN / RN, Bn / BG, En), 256>>>(out);
}

// round 7
// speedup vs baseline: 1.2254x; 1.2254x over previous
#include <cuda_runtime.h>
#include <math.h>

#define En 2
#define NN 512
#define Bn 64
#define Tt 12
#define Kk 64
#define RN 4     // rows per block tile in main kernel
#define BG 4     // batches per block in main kernel
#define ESTR (Bn * NN * NN)   // e-stride in output

// Scratch (static device arrays: allocation-free)
__device__ __align__(16) float g_sup[En * NN * NN];      // relu(supports + adaptive)  (2 MB)
__device__ __align__(16) float g_nodesT[Bn * NN * Tt];   // normalized nodes, [b][n][t] (1.5 MB)
__device__ __align__(16) float g_nodesN[Bn * Tt * NN];   // normalized nodes, [b][t][n] (1.5 MB)

// ---------------- packed f32x2 + MUFU helpers ----------------
__device__ __forceinline__ unsigned long long pack2(float a, float b) {
    unsigned long long r;
    asm("mov.b64 %0, {%1, %2};" : "=l"(r) : "f"(a), "f"(b));
    return r;
}
__device__ __forceinline__ void unpack2(unsigned long long p, float& a, float& b) {
    asm("mov.b64 {%0, %1}, %2;" : "=f"(a), "=f"(b) : "l"(p));
}
__device__ __forceinline__ unsigned long long fma2_(unsigned long long a, unsigned long long b, unsigned long long c) {
    unsigned long long d;
    asm("fma.rn.f32x2 %0, %1, %2, %3;" : "=l"(d) : "l"(a), "l"(b), "l"(c));
    return d;
}
__device__ __forceinline__ unsigned long long mul2_(unsigned long long a, unsigned long long b) {
    unsigned long long d;
    asm("mul.rn.f32x2 %0, %1, %2;" : "=l"(d) : "l"(a), "l"(b));
    return d;
}
__device__ __forceinline__ unsigned long long add2_(unsigned long long a, unsigned long long b) {
    unsigned long long d;
    asm("add.rn.f32x2 %0, %1, %2;" : "=l"(d) : "l"(a), "l"(b));
    return d;
}
__device__ __forceinline__ float sqrt_ap(float x) { float r; asm("sqrt.approx.f32 %0, %1;" : "=f"(r) : "f"(x)); return r; }
__device__ __forceinline__ float ex2_neg(float x) { float r; asm("ex2.approx.f32 %0, %1;"  : "=f"(r) : "f"(-x)); return r; }
__device__ __forceinline__ float rcp_ap(float x)  { float r; asm("rcp.approx.f32 %0, %1;"  : "=f"(r) : "f"(x)); return r; }
__device__ __forceinline__ float hadd2(unsigned long long p) {
    float a, b; unpack2(p, a, b); return a + b;
}

// ---------------------------------------------------------------------------
// Kernel A (fused prep):
//   z = 0,1 : g_sup[e] = relu(supports + u * diag(s*softplus(bias)) * v^T)
//   z = 2   : L2-normalize node histories -> g_nodesT [b][n][t] + g_nodesN [b][t][n]
// ---------------------------------------------------------------------------
__global__ void __launch_bounds__(256) prep_kernel(const float* __restrict__ supports,
                                                   const float* __restrict__ u,
                                                   const float* __restrict__ s,
                                                   const float* __restrict__ v,
                                                   const float* __restrict__ bias,
                                                   const float* __restrict__ inputs) {
    const int tid = threadIdx.x;

    if (blockIdx.z == 2) {
        const int g = (blockIdx.y * 8 + blockIdx.x) * 256 + tid;
        #pragma unroll
        for (int it = 0; it < 2; it++) {
            const int i = g + it * 16384;      // b*512 + n
            const int b = i >> 9, n = i & (NN - 1);
            float x[Tt];
            float ss = 0.f;
            #pragma unroll
            for (int t = 0; t < Tt; t++) {
                x[t] = inputs[(((b * Tt + t) * NN) + n) * 2];
                ss = fmaf(x[t], x[t], ss);
            }
            float inv = 1.0f / fmaxf(sqrtf(ss), 1e-12f);
            #pragma unroll
            for (int t = 0; t < Tt; t++) x[t] *= inv;
            float* dst = g_nodesT + (b * NN + n) * Tt;
            *(float4*)(dst)     = make_float4(x[0], x[1], x[2],  x[3]);
            *(float4*)(dst + 4) = make_float4(x[4], x[5], x[6],  x[7]);
            *(float4*)(dst + 8) = make_float4(x[8], x[9], x[10], x[11]);
            #pragma unroll
            for (int t = 0; t < Tt; t++)
                g_nodesN[(b * Tt + t) * NN + n] = x[t];
        }
        return;
    }

    __shared__ float su_t[Kk][68];
    __shared__ float sv_t[Kk][68];
    __shared__ float ssc[Kk];

    const int e  = blockIdx.z;
    const int n0 = blockIdx.y * 64;
    const int m0 = blockIdx.x * 64;

    if (tid < 64) {
        float bx = bias[e * Kk + tid];
        float sp = (bx > 20.f) ? bx : log1pf(__expf(bx));   // softplus
        ssc[tid] = s[e * Kk + tid] * sp;
    }
    __syncthreads();

    #pragma unroll
    for (int j = 0; j < 4; j++) {
        int idx = tid + j * 256;
        int row = idx & 63;
        int kq  = idx >> 6;
        float4 uv = *(const float4*)(u + (e * NN + n0 + row) * Kk + kq * 4);
        float4 vv = *(const float4*)(v + (e * NN + m0 + row) * Kk + kq * 4);
        su_t[kq * 4 + 0][row] = uv.x * ssc[kq * 4 + 0];
        su_t[kq * 4 + 1][row] = uv.y * ssc[kq * 4 + 1];
        su_t[kq * 4 + 2][row] = uv.z * ssc[kq * 4 + 2];
        su_t[kq * 4 + 3][row] = uv.w * ssc[kq * 4 + 3];
        sv_t[kq * 4 + 0][row] = vv.x;
        sv_t[kq * 4 + 1][row] = vv.y;
        sv_t[kq * 4 + 2][row] = vv.z;
        sv_t[kq * 4 + 3][row] = vv.w;
    }
    __syncthreads();

    const int ry = (tid >> 4) << 2;
    const int rx = (tid & 15) << 2;
    float acc[4][4] = {};

    #pragma unroll
    for (int k = 0; k < 64; k++) {
        float4 a  = *(const float4*)&su_t[k][ry];
        float4 bq = *(const float4*)&sv_t[k][rx];
        acc[0][0] = fmaf(a.x, bq.x, acc[0][0]); acc[0][1] = fmaf(a.x, bq.y, acc[0][1]);
        acc[0][2] = fmaf(a.x, bq.z, acc[0][2]); acc[0][3] = fmaf(a.x, bq.w, acc[0][3]);
        acc[1][0] = fmaf(a.y, bq.x, acc[1][0]); acc[1][1] = fmaf(a.y, bq.y, acc[1][1]);
        acc[1][2] = fmaf(a.y, bq.z, acc[1][2]); acc[1][3] = fmaf(a.y, bq.w, acc[1][3]);
        acc[2][0] = fmaf(a.z, bq.x, acc[2][0]); acc[2][1] = fmaf(a.z, bq.y, acc[2][1]);
        acc[2][2] = fmaf(a.z, bq.z, acc[2][2]); acc[2][3] = fmaf(a.z, bq.w, acc[2][3]);
        acc[3][0] = fmaf(a.w, bq.x, acc[3][0]); acc[3][1] = fmaf(a.w, bq.y, acc[3][1]);
        acc[3][2] = fmaf(a.w, bq.z, acc[3][2]); acc[3][3] = fmaf(a.w, bq.w, acc[3][3]);
    }

    #pragma unroll
    for (int i = 0; i < 4; i++) {
        int base = (e * NN + n0 + ry + i) * NN + m0 + rx;
        float4 sp = *(const float4*)(supports + base);
        float4 o;
        o.x = fmaxf(sp.x + acc[i][0], 0.f);
        o.y = fmaxf(sp.y + acc[i][1], 0.f);
        o.z = fmaxf(sp.z + acc[i][2], 0.f);
        o.w = fmaxf(sp.w + acc[i][3], 0.f);
        *(float4*)(g_sup + base) = o;
    }
}

// ---------------------------------------------------------------------------
// Kernel C: fused main pass. RN=4 rows x BOTH experts per block (no redundant
// distance work), low register footprint -> 3 blocks/SM.
// 256 threads, each owns an m-pair (packed f32x2).
// ---------------------------------------------------------------------------
__global__ void __launch_bounds__(256, 3)
main_kernel(float* __restrict__ out) {
    __shared__ float ps[2 * RN][256];                 // row-sum partials, 8 KB
    __shared__ unsigned long long xd[RN * Tt];        // packed {xn,xn} per tile row
    __shared__ float invs[2 * RN];

    const int tid  = threadIdx.x;
    const int lane = tid & 31;
    const int warp = tid >> 5;
    const int n0 = blockIdx.x * RN;
    const int b0 = blockIdx.y * BG;
    const int m0 = tid * 2;

    // sup (relu'd) in registers: batch-invariant, this thread's m-pair, both e
    unsigned long long sup0[RN], sup1[RN];
    #pragma unroll
    for (int r = 0; r < RN; r++) {
        sup0[r] = *(const unsigned long long*)(g_sup + (n0 + r) * NN + m0);
        sup1[r] = *(const unsigned long long*)(g_sup + NN * NN + (n0 + r) * NN + m0);
    }

    // 2 * (ln2^-1)^2
    const float C = 4.1627379620112154f;
    const unsigned long long CM = pack2(-C, -C);
    const unsigned long long CP = pack2( C,  C);

    for (int bi = 0; bi < BG; ++bi) {
        const int b = b0 + bi;

        // duplicated row-node table (48 values)
        if (tid < RN * Tt) {
            int r = tid / Tt, t = tid - r * Tt;
            float xv = g_nodesT[b * (NN * Tt) + (n0 + r) * Tt + t];
            xd[tid] = pack2(xv, xv);
        }

        // xm pair: 12 coalesced LDG.64, already packed {x[t][m0], x[t][m0+1]}
        unsigned long long xm2[Tt];
        {
            const unsigned long long* xb =
                (const unsigned long long*)(g_nodesN + b * (Tt * NN)) + tid;
            #pragma unroll
            for (int t = 0; t < Tt; t++)
                xm2[t] = xb[t * (NN / 2)];
        }
        __syncthreads();   // xd ready; also fences prev-batch writeout/reduce

        unsigned long long val0[RN], val1[RN];
        #pragma unroll
        for (int r = 0; r < RN; r++) {
            const ulonglong2* xdp = (const ulonglong2*)&xd[r * Tt];
            ulonglong2 q0 = xdp[0], q1 = xdp[1], q2 = xdp[2];
            ulonglong2 q3 = xdp[3], q4 = xdp[4], q5 = xdp[5];
            unsigned long long pa = mul2_(xm2[0], q0.x);
            unsigned long long pb = mul2_(xm2[1], q0.y);
            pa = fma2_(xm2[2],  q1.x, pa);  pb = fma2_(xm2[3],  q1.y, pb);
            pa = fma2_(xm2[4],  q2.x, pa);  pb = fma2_(xm2[5],  q2.y, pb);
            pa = fma2_(xm2[6],  q3.x, pa);  pb = fma2_(xm2[7],  q3.y, pb);
            pa = fma2_(xm2[8],  q4.x, pa);  pb = fma2_(xm2[9],  q4.y, pb);
            pa = fma2_(xm2[10], q5.x, pa);  pb = fma2_(xm2[11], q5.y, pb);
            unsigned long long inner2 = add2_(pa, pb);
            unsigned long long d2p = fma2_(inner2, CM, CP);  // (1.4427*d)^2 packed
            float d20, d21;
            unpack2(d2p, d20, d21);
            d20 = fmaxf(d20, 0.f);
            d21 = fmaxf(d21, 0.f);
            float f0 = ex2_neg(sqrt_ap(d20)) + 1.0f;
            float f1 = ex2_neg(sqrt_ap(d21)) + 1.0f;
            unsigned long long fp = pack2(f0, f1);

            val0[r] = mul2_(fp, sup0[r]);
            val1[r] = mul2_(fp, sup1[r]);
            ps[r * 2][tid]     = hadd2(val0[r]);
            ps[r * 2 + 1][tid] = hadd2(val1[r]);
        }
        __syncthreads();

        // One warp per (row, e): 8 warps <-> 8 sums, 256 partials each
        {
            const float4* p0 = (const float4*)ps[warp];
            float4 v0 = p0[lane];
            float4 v1 = p0[lane + 32];
            float sum = (v0.x + v0.y) + (v0.z + v0.w)
                      + (v1.x + v1.y) + (v1.z + v1.w);
            #pragma unroll
            for (int o = 16; o > 0; o >>= 1)
                sum += __shfl_xor_sync(0xffffffffu, sum, o);
            if (lane == 0)
                invs[warp] = rcp_ap(fmaxf(sum, 1e-12f));
        }
        __syncthreads();

        // Direct register -> gmem writeout (STG.64, coalesced)
        float* ob = out + (b * NN + n0) * NN + m0;
        #pragma unroll
        for (int r = 0; r < RN; r++) {
            float iv0 = invs[r * 2], iv1 = invs[r * 2 + 1];
            *(unsigned long long*)(ob + r * NN) =
                mul2_(val0[r], pack2(iv0, iv0));
            *(unsigned long long*)(ob + ESTR + r * NN) =
                mul2_(val1[r], pack2(iv1, iv1));
        }
    }
}

// ---------------------------------------------------------------------------
extern "C" void kernel_launch(void* const* d_in, const int* in_sizes, int n_in,
                              void* d_out, int out_size) {
    const float* supports = (const float*)d_in[0];  // [2,512,512]
    const float* u        = (const float*)d_in[1];  // [2,512,64]
    const float* s        = (const float*)d_in[2];  // [2,64]
    const float* v        = (const float*)d_in[3];  // [2,512,64]
    const float* bias     = (const float*)d_in[4];  // [2,64]
    const float* inputs   = (const float*)d_in[5];  // [64,12,512,2]
    float* out = (float*)d_out;                     // [2,64,512,512]

    prep_kernel<<<dim3(8, 8, 3), 256>>>(supports, u, s, v, bias, inputs);
    main_kernel<<<dim3(NN / RN, Bn / BG), 256>>>(out);
}

// round 8
// speedup vs baseline: 1.3119x; 1.0705x over previous
#include <cuda_runtime.h>
#include <math.h>

#define En 2
#define NN 512
#define Bn 64
#define Tt 12
#define Kk 64
#define RN 4     // rows per block tile in main kernel
#define BG 4     // batches per block in main kernel
#define ESTR (Bn * NN * NN)   // e-stride in output

// Scratch (static device arrays: allocation-free)
__device__ __align__(16) float g_sup[En * NN * NN];      // relu(supports + adaptive)  (2 MB)
__device__ __align__(16) float g_nodesT[Bn * NN * Tt];   // normalized nodes, [b][n][t] (1.5 MB)
__device__ __align__(16) float g_nodesN[Bn * Tt * NN];   // normalized nodes, [b][t][n] (1.5 MB)

// ---------------- packed f32x2 + MUFU helpers ----------------
__device__ __forceinline__ unsigned long long pack2(float a, float b) {
    unsigned long long r;
    asm("mov.b64 %0, {%1, %2};" : "=l"(r) : "f"(a), "f"(b));
    return r;
}
__device__ __forceinline__ void unpack2(unsigned long long p, float& a, float& b) {
    asm("mov.b64 {%0, %1}, %2;" : "=f"(a), "=f"(b) : "l"(p));
}
__device__ __forceinline__ unsigned long long fma2_(unsigned long long a, unsigned long long b, unsigned long long c) {
    unsigned long long d;
    asm("fma.rn.f32x2 %0, %1, %2, %3;" : "=l"(d) : "l"(a), "l"(b), "l"(c));
    return d;
}
__device__ __forceinline__ unsigned long long mul2_(unsigned long long a, unsigned long long b) {
    unsigned long long d;
    asm("mul.rn.f32x2 %0, %1, %2;" : "=l"(d) : "l"(a), "l"(b));
    return d;
}
__device__ __forceinline__ unsigned long long add2_(unsigned long long a, unsigned long long b) {
    unsigned long long d;
    asm("add.rn.f32x2 %0, %1, %2;" : "=l"(d) : "l"(a), "l"(b));
    return d;
}
__device__ __forceinline__ float sqrt_ap(float x) { float r; asm("sqrt.approx.f32 %0, %1;" : "=f"(r) : "f"(x)); return r; }
__device__ __forceinline__ float ex2_neg(float x) { float r; asm("ex2.approx.f32 %0, %1;"  : "=f"(r) : "f"(-x)); return r; }
__device__ __forceinline__ float rcp_ap(float x)  { float r; asm("rcp.approx.f32 %0, %1;"  : "=f"(r) : "f"(x)); return r; }
__device__ __forceinline__ float hadd2(unsigned long long p) {
    float a, b; unpack2(p, a, b); return a + b;
}

// ---------------------------------------------------------------------------
// Kernel A (fused prep), 512 threads:
//   z = 0,1 : g_sup[e] = relu(supports + u * diag(s*softplus(bias)) * v^T)
//             64x64 tile, 2x4 micro-tile
//   z = 2   : L2-normalize node histories -> g_nodesT [b][n][t] + g_nodesN [b][t][n]
// ---------------------------------------------------------------------------
__global__ void __launch_bounds__(512) prep_kernel(const float* __restrict__ supports,
                                                   const float* __restrict__ u,
                                                   const float* __restrict__ s,
                                                   const float* __restrict__ v,
                                                   const float* __restrict__ bias,
                                                   const float* __restrict__ inputs) {
    const int tid = threadIdx.x;

    if (blockIdx.z == 2) {
        // ---- nodes path: 64 blocks x 512 threads, 1 item each ----
        const int i = (blockIdx.y * 8 + blockIdx.x) * 512 + tid;  // b*512 + n
        const int b = i >> 9, n = i & (NN - 1);
        float x[Tt];
        float ss = 0.f;
        #pragma unroll
        for (int t = 0; t < Tt; t++) {
            x[t] = inputs[(((b * Tt + t) * NN) + n) * 2];
            ss = fmaf(x[t], x[t], ss);
        }
        float inv = 1.0f / fmaxf(sqrtf(ss), 1e-12f);
        #pragma unroll
        for (int t = 0; t < Tt; t++) x[t] *= inv;
        float* dst = g_nodesT + (b * NN + n) * Tt;
        *(float4*)(dst)     = make_float4(x[0], x[1], x[2],  x[3]);
        *(float4*)(dst + 4) = make_float4(x[4], x[5], x[6],  x[7]);
        *(float4*)(dst + 8) = make_float4(x[8], x[9], x[10], x[11]);
        #pragma unroll
        for (int t = 0; t < Tt; t++)
            g_nodesN[(b * Tt + t) * NN + n] = x[t];
        return;
    }

    __shared__ float su_t[Kk][68];   // [k][n], scaled
    __shared__ float sv_t[Kk][68];   // [k][m]
    __shared__ float ssc[Kk];

    const int e  = blockIdx.z;
    const int n0 = blockIdx.y * 64;
    const int m0 = blockIdx.x * 64;

    if (tid < 64) {
        float bx = bias[e * Kk + tid];
        float sp = (bx > 20.f) ? bx : log1pf(__expf(bx));   // softplus
        ssc[tid] = s[e * Kk + tid] * sp;
    }
    __syncthreads();

    // Fill smem transposed: 1024 float4 per array, 512 threads -> 2 each
    #pragma unroll
    for (int j = 0; j < 2; j++) {
        int idx = tid + j * 512;
        int row = idx & 63;
        int kq  = idx >> 6;        // 0..15
        float4 uv = *(const float4*)(u + (e * NN + n0 + row) * Kk + kq * 4);
        float4 vv = *(const float4*)(v + (e * NN + m0 + row) * Kk + kq * 4);
        su_t[kq * 4 + 0][row] = uv.x * ssc[kq * 4 + 0];
        su_t[kq * 4 + 1][row] = uv.y * ssc[kq * 4 + 1];
        su_t[kq * 4 + 2][row] = uv.z * ssc[kq * 4 + 2];
        su_t[kq * 4 + 3][row] = uv.w * ssc[kq * 4 + 3];
        sv_t[kq * 4 + 0][row] = vv.x;
        sv_t[kq * 4 + 1][row] = vv.y;
        sv_t[kq * 4 + 2][row] = vv.z;
        sv_t[kq * 4 + 3][row] = vv.w;
    }
    __syncthreads();

    // 2x4 micro-tile: 32 row-groups x 16 col-groups
    const int ry = (tid >> 4) << 1;       // 0..62, step 2
    const int rx = (tid & 15) << 2;       // 0..60, step 4
    float acc[2][4] = {};

    #pragma unroll
    for (int k = 0; k < 64; k++) {
        float2 a  = *(const float2*)&su_t[k][ry];
        float4 bq = *(const float4*)&sv_t[k][rx];
        acc[0][0] = fmaf(a.x, bq.x, acc[0][0]); acc[0][1] = fmaf(a.x, bq.y, acc[0][1]);
        acc[0][2] = fmaf(a.x, bq.z, acc[0][2]); acc[0][3] = fmaf(a.x, bq.w, acc[0][3]);
        acc[1][0] = fmaf(a.y, bq.x, acc[1][0]); acc[1][1] = fmaf(a.y, bq.y, acc[1][1]);
        acc[1][2] = fmaf(a.y, bq.z, acc[1][2]); acc[1][3] = fmaf(a.y, bq.w, acc[1][3]);
    }

    #pragma unroll
    for (int i = 0; i < 2; i++) {
        int base = (e * NN + n0 + ry + i) * NN + m0 + rx;
        float4 sp = *(const float4*)(supports + base);
        float4 o;
        o.x = fmaxf(sp.x + acc[i][0], 0.f);
        o.y = fmaxf(sp.y + acc[i][1], 0.f);
        o.z = fmaxf(sp.z + acc[i][2], 0.f);
        o.w = fmaxf(sp.w + acc[i][3], 0.f);
        *(float4*)(g_sup + base) = o;
    }
}

// ---------------------------------------------------------------------------
// Kernel C: fused main pass, software-pipelined.
// RN=4 rows x BOTH experts per block; xd staged once for all BG batches;
// xm2 LDGs issued before prev-batch writeout (latency shadow);
// 2 barriers per batch (ps-ready, invs-ready), double-buffered invs.
// ---------------------------------------------------------------------------
__global__ void __launch_bounds__(256, 3)
main_kernel(float* __restrict__ out) {
    __shared__ float ps[2 * RN][256];                     // row-sum partials, 8 KB
    __shared__ unsigned long long xd[BG * RN * Tt];       // packed {xn,xn}, all batches
    __shared__ float invs[2][2 * RN];                     // double-buffered

    const int tid  = threadIdx.x;
    const int lane = tid & 31;
    const int warp = tid >> 5;
    const int n0 = blockIdx.x * RN;
    const int b0 = blockIdx.y * BG;
    const int m0 = tid * 2;

    // sup (relu'd) in registers: batch-invariant, this thread's m-pair, both e
    unsigned long long sup0[RN], sup1[RN];
    #pragma unroll
    for (int r = 0; r < RN; r++) {
        sup0[r] = *(const unsigned long long*)(g_sup + (n0 + r) * NN + m0);
        sup1[r] = *(const unsigned long long*)(g_sup + NN * NN + (n0 + r) * NN + m0);
    }

    // Stage duplicated row-node tables for ALL batches (192 entries)
    if (tid < BG * RN * Tt) {
        int bl  = tid / (RN * Tt);
        int rem = tid - bl * (RN * Tt);
        int r = rem / Tt, t = rem - r * Tt;
        float xv = g_nodesT[(b0 + bl) * (NN * Tt) + (n0 + r) * Tt + t];
        xd[tid] = pack2(xv, xv);
    }
    __syncthreads();

    // 2 * (ln2^-1)^2
    const float C = 4.1627379620112154f;
    const unsigned long long CM = pack2(-C, -C);
    const unsigned long long CP = pack2( C,  C);

    unsigned long long val0[RN], val1[RN];

    #pragma unroll
    for (int bi = 0; bi < BG; ++bi) {
        // 1) issue this batch's xm2 loads FIRST (12 coalesced LDG.64)
        unsigned long long xm2[Tt];
        {
            const unsigned long long* xb =
                (const unsigned long long*)(g_nodesN + (b0 + bi) * (Tt * NN)) + tid;
            #pragma unroll
            for (int t = 0; t < Tt; t++)
                xm2[t] = xb[t * (NN / 2)];
        }

        // 2) previous batch's writeout in the LDG shadow
        if (bi > 0) {
            const float* ivp = invs[(bi - 1) & 1];
            float* ob = out + ((b0 + bi - 1) * NN + n0) * NN + m0;
            #pragma unroll
            for (int r = 0; r < RN; r++) {
                float iv0 = ivp[r * 2], iv1 = ivp[r * 2 + 1];
                *(unsigned long long*)(ob + r * NN) =
                    mul2_(val0[r], pack2(iv0, iv0));
                *(unsigned long long*)(ob + ESTR + r * NN) =
                    mul2_(val1[r], pack2(iv1, iv1));
            }
        }

        // 3) compute vals + partial sums
        #pragma unroll
        for (int r = 0; r < RN; r++) {
            const ulonglong2* xdp = (const ulonglong2*)&xd[(bi * RN + r) * Tt];
            ulonglong2 q0 = xdp[0], q1 = xdp[1], q2 = xdp[2];
            ulonglong2 q3 = xdp[3], q4 = xdp[4], q5 = xdp[5];
            unsigned long long pa = mul2_(xm2[0], q0.x);
            unsigned long long pb = mul2_(xm2[1], q0.y);
            pa = fma2_(xm2[2],  q1.x, pa);  pb = fma2_(xm2[3],  q1.y, pb);
            pa = fma2_(xm2[4],  q2.x, pa);  pb = fma2_(xm2[5],  q2.y, pb);
            pa = fma2_(xm2[6],  q3.x, pa);  pb = fma2_(xm2[7],  q3.y, pb);
            pa = fma2_(xm2[8],  q4.x, pa);  pb = fma2_(xm2[9],  q4.y, pb);
            pa = fma2_(xm2[10], q5.x, pa);  pb = fma2_(xm2[11], q5.y, pb);
            unsigned long long inner2 = add2_(pa, pb);
            unsigned long long d2p = fma2_(inner2, CM, CP);  // (1.4427*d)^2 packed
            float d20, d21;
            unpack2(d2p, d20, d21);
            d20 = fmaxf(d20, 0.f);
            d21 = fmaxf(d21, 0.f);
            float f0 = ex2_neg(sqrt_ap(d20)) + 1.0f;
            float f1 = ex2_neg(sqrt_ap(d21)) + 1.0f;
            unsigned long long fp = pack2(f0, f1);

            val0[r] = mul2_(fp, sup0[r]);
            val1[r] = mul2_(fp, sup1[r]);
            ps[r * 2][tid]     = hadd2(val0[r]);
            ps[r * 2 + 1][tid] = hadd2(val1[r]);
        }
        __syncthreads();   // ps ready

        // 4) one warp per (row, e)
        {
            const float4* p0 = (const float4*)ps[warp];
            float4 v0 = p0[lane];
            float4 v1 = p0[lane + 32];
            float sum = (v0.x + v0.y) + (v0.z + v0.w)
                      + (v1.x + v1.y) + (v1.z + v1.w);
            #pragma unroll
            for (int o = 16; o > 0; o >>= 1)
                sum += __shfl_xor_sync(0xffffffffu, sum, o);
            if (lane == 0)
                invs[bi & 1][warp] = rcp_ap(fmaxf(sum, 1e-12f));
        }
        __syncthreads();   // invs ready; also guards ps reuse next iter
    }

    // Epilogue: last batch's writeout
    {
        const float* ivp = invs[(BG - 1) & 1];
        float* ob = out + ((b0 + BG - 1) * NN + n0) * NN + m0;
        #pragma unroll
        for (int r = 0; r < RN; r++) {
            float iv0 = ivp[r * 2], iv1 = ivp[r * 2 + 1];
            *(unsigned long long*)(ob + r * NN) =
                mul2_(val0[r], pack2(iv0, iv0));
            *(unsigned long long*)(ob + ESTR + r * NN) =
                mul2_(val1[r], pack2(iv1, iv1));
        }
    }
}

// ---------------------------------------------------------------------------
extern "C" void kernel_launch(void* const* d_in, const int* in_sizes, int n_in,
                              void* d_out, int out_size) {
    const float* supports = (const float*)d_in[0];  // [2,512,512]
    const float* u        = (const float*)d_in[1];  // [2,512,64]
    const float* s        = (const float*)d_in[2];  // [2,64]
    const float* v        = (const float*)d_in[3];  // [2,512,64]
    const float* bias     = (const float*)d_in[4];  // [2,64]
    const float* inputs   = (const float*)d_in[5];  // [64,12,512,2]
    float* out = (float*)d_out;                     // [2,64,512,512]

    prep_kernel<<<dim3(8, 8, 3), 512>>>(supports, u, s, v, bias, inputs);
    main_kernel<<<dim3(NN / RN, Bn / BG), 256>>>(out);
}